// round 1
// baseline (speedup 1.0000x reference)
#include <cuda_runtime.h>
#include <math.h>
#include <stdint.h>

// Problem constants (shapes are fixed by the dataset; dims derived from in_sizes
// where cheap, but HC/HID are structural).
#define HC   256     // H*C = 2*128
#define HID  256
#define MAXE 8192    // cap on edges hitting the target node (E/N ~ 8 expected)

// __device__ scratch (no allocations allowed)
__device__ unsigned long long g_pack;      // packed argmax of labels
__device__ int                g_count;     // number of matched edges
__device__ int                g_edges[MAXE];
__device__ float              g_alpha[MAXE * 2];

// ---------------------------------------------------------------------------
__global__ void init_kernel() {
    g_pack  = 0ULL;
    g_count = 0;
}

// argmax(labels) with first-index tiebreak: pack (val order-preserving) high,
// (~idx) low so larger packed == larger val, then smaller idx.
__global__ void argmax_kernel(const int* __restrict__ labels, int n) {
    int i = blockIdx.x * blockDim.x + threadIdx.x;
    if (i >= n) return;
    unsigned uval = (unsigned)labels[i] ^ 0x80000000u;
    unsigned long long packed =
        ((unsigned long long)uval << 32) | (unsigned long long)(0xFFFFFFFFu - (unsigned)i);
    atomicMax(&g_pack, packed);
}

__global__ void filter_kernel(const int* __restrict__ dst, int E) {
    int target = (int)(0xFFFFFFFFu - (unsigned)(g_pack & 0xFFFFFFFFull));
    int i = blockIdx.x * blockDim.x + threadIdx.x;
    if (i >= E) return;
    if (dst[i] == target) {
        int p = atomicAdd(&g_count, 1);
        if (p < MAXE) g_edges[p] = i;
    }
}

// One block, 256 threads: full GATv2 row for the target node + ReLU + FC.
__global__ void compute_kernel(
    const float* __restrict__ x,        // [N,2]
    const int*   __restrict__ src,      // [E]
    const float* __restrict__ eattr,    // [E,1]
    const float* __restrict__ Wl,       // [2,256]
    const float* __restrict__ bl,       // [256]
    const float* __restrict__ Wr,       // [2,256]
    const float* __restrict__ br,       // [256]
    const float* __restrict__ We,       // [1,256]
    const float* __restrict__ att,      // [2,128] flat [256]
    const float* __restrict__ bo,       // [256]
    const float* __restrict__ Wfc,      // [256,256]
    const float* __restrict__ bfc,      // [256]
    float*       __restrict__ out)      // [256]
{
    __shared__ float sXr[HC];
    __shared__ float sRed[HC];
    __shared__ float sTe[HC];
    __shared__ int   sCnt;

    const int j = threadIdx.x;

    if (j == 0) {
        int cnt = g_count;
        if (cnt > MAXE) cnt = MAXE;
        // sort matched edges ascending for bit-deterministic summation order
        for (int a = 1; a < cnt; a++) {
            int key = g_edges[a];
            int b = a - 1;
            while (b >= 0 && g_edges[b] > key) { g_edges[b + 1] = g_edges[b]; b--; }
            g_edges[b + 1] = key;
        }
        sCnt = cnt;
    }
    __syncthreads();
    const int cnt = sCnt;
    const int target = (int)(0xFFFFFFFFu - (unsigned)(g_pack & 0xFFFFFFFFull));

    // xr for target node
    const float xt0 = x[2 * target], xt1 = x[2 * target + 1];
    sXr[j] = xt0 * Wr[j] + xt1 * Wr[HC + j] + br[j];
    __syncthreads();

    const float Wl0j = Wl[j], Wl1j = Wl[HC + j], blj = bl[j];
    const float Wej  = We[j], attj = att[j];

    // attention logits per matched edge (block reduce per 128-channel head)
    for (int e = 0; e < cnt; e++) {
        const int eid = g_edges[e];
        const int s   = src[eid];
        const float ea = eattr[eid];
        const float xl = x[2 * s] * Wl0j + x[2 * s + 1] * Wl1j + blj;
        float m = xl + sXr[j] + ea * Wej;
        float sv = m > 0.0f ? m : 0.2f * m;   // leaky_relu(0.2)
        sRed[j] = sv * attj;
        __syncthreads();
        #pragma unroll
        for (int st = 64; st > 0; st >>= 1) {
            if ((j & 127) < st) sRed[j] += sRed[j + st];
            __syncthreads();
        }
        if (j < 2) g_alpha[e * 2 + j] = sRed[j * 128];
        __syncthreads();
    }

    // per-head softmax over matched edges (reference quirks preserved)
    if (j < 2) {
        float amax = -INFINITY;
        for (int e = 0; e < cnt; e++) amax = fmaxf(amax, g_alpha[e * 2 + j]);
        if (!isfinite(amax)) amax = 0.0f;
        float den = 0.0f;
        for (int e = 0; e < cnt; e++) den += expf(g_alpha[e * 2 + j] - amax);
        const float inv = 1.0f / (den + 1e-16f);
        for (int e = 0; e < cnt; e++)
            g_alpha[e * 2 + j] = expf(g_alpha[e * 2 + j] - amax) * inv;
    }
    __syncthreads();

    // weighted message sum, bias, ReLU
    float acc = 0.0f;
    const int h = j >> 7;
    for (int e = 0; e < cnt; e++) {
        const int eid = g_edges[e];
        const int s   = src[eid];
        const float xl = x[2 * s] * Wl0j + x[2 * s + 1] * Wl1j + blj;
        acc += xl * g_alpha[e * 2 + h];
    }
    sTe[j] = fmaxf(acc + bo[j], 0.0f);
    __syncthreads();

    // final FC: out[j] = bfc[j] + sum_k te[k] * Wfc[k,j]  (coalesced over j)
    float o = bfc[j];
    #pragma unroll 8
    for (int k = 0; k < HC; k++) o += sTe[k] * Wfc[k * HID + j];
    out[j] = o;
}

// ---------------------------------------------------------------------------
extern "C" void kernel_launch(void* const* d_in, const int* in_sizes, int n_in,
                              void* d_out, int out_size)
{
    const float* x          = (const float*)d_in[0];
    const int*   edge_index = (const int*)  d_in[1];
    const float* edge_attr  = (const float*)d_in[2];
    const int*   labels     = (const int*)  d_in[3];
    // conv1 params d_in[4..10] are dead code in the reference (h1 unused)
    const float* Wl2 = (const float*)d_in[11];
    const float* bl2 = (const float*)d_in[12];
    const float* Wr2 = (const float*)d_in[13];
    const float* br2 = (const float*)d_in[14];
    const float* We2 = (const float*)d_in[15];
    const float* att2= (const float*)d_in[16];
    const float* bo2 = (const float*)d_in[17];
    const float* Wfc = (const float*)d_in[18];
    const float* bfc = (const float*)d_in[19];
    float* out = (float*)d_out;

    const int N = in_sizes[0] / 2;
    const int E = in_sizes[1] / 2;
    const int* src = edge_index;        // row 0
    const int* dst = edge_index + E;    // row 1

    init_kernel<<<1, 1>>>();
    argmax_kernel<<<(N + 255) / 256, 256>>>(labels, N);
    filter_kernel<<<(E + 255) / 256, 256>>>(dst, E);
    compute_kernel<<<1, 256>>>(x, src, edge_attr,
                               Wl2, bl2, Wr2, br2, We2, att2, bo2,
                               Wfc, bfc, out);
}

// round 3
// speedup vs baseline: 3.1318x; 3.1318x over previous
#include <cuda_runtime.h>
#include <math.h>
#include <stdint.h>

#define HC    256      // H*C = 2*128
#define HID   256
#define MAXB1 512      // max argmax partial blocks
#define G2    148      // filter grid (one wave)
#define CAP   128      // per-filter-block match capacity
#define MAXED 256      // max edges into target handled by compute (E[matches]~8)

// __device__ scratch — every field is written unconditionally each replay,
// so no init/reset kernel is needed.
__device__ unsigned long long g_pmax[MAXB1];
__device__ int                g_target;
__device__ int                g_cnt[G2];
__device__ int                g_edges[G2 * CAP];

// ---------------------------------------------------------------------------
// K1: per-block partial argmax of labels. pack = (val order-preserved)<<32 | ~idx
// so larger packed == larger val, then smaller idx (first-index tiebreak).
__global__ void argmax_part_kernel(const int* __restrict__ labels, int n) {
    const int t = threadIdx.x;
    int idx = blockIdx.x * (blockDim.x * 8) + t;
    unsigned long long best = 0ULL;
    #pragma unroll
    for (int i = 0; i < 8; i++) {
        if (idx < n) {
            unsigned uval = (unsigned)labels[idx] ^ 0x80000000u;
            unsigned long long p = ((unsigned long long)uval << 32)
                                 | (unsigned long long)(0xFFFFFFFFu - (unsigned)idx);
            best = p > best ? p : best;
        }
        idx += blockDim.x;
    }
    __shared__ unsigned long long s[256];
    s[t] = best;
    __syncthreads();
    #pragma unroll
    for (int st = 128; st > 0; st >>= 1) {
        if (t < st) s[t] = s[t] > s[t + st] ? s[t] : s[t + st];
        __syncthreads();
    }
    if (t == 0) g_pmax[blockIdx.x] = s[0];
}

// ---------------------------------------------------------------------------
// K2: each block finishes the argmax reduction (cheap, L2), then scans its
// slice of dst for edges into the target. Per-block compaction — count and
// list are written unconditionally, ordering fixed later by a tiny sort.
__global__ void filter_kernel(const int* __restrict__ dst, int E, int nb1) {
    __shared__ unsigned long long sm[256];
    __shared__ int scnt;
    const int t = threadIdx.x;

    unsigned long long best = 0ULL;
    for (int i = t; i < nb1; i += 256) {
        unsigned long long v = g_pmax[i];
        best = v > best ? v : best;
    }
    sm[t] = best;
    if (t == 0) scnt = 0;
    __syncthreads();
    #pragma unroll
    for (int st = 128; st > 0; st >>= 1) {
        if (t < st) sm[t] = sm[t] > sm[t + st] ? sm[t] : sm[t + st];
        __syncthreads();
    }
    const int target = (int)(0xFFFFFFFFu - (unsigned)(sm[0] & 0xFFFFFFFFull));
    if (blockIdx.x == 0 && t == 0) g_target = target;

    const int per = (E + G2 - 1) / G2;
    const int lo = blockIdx.x * per;
    const int hi = min(E, lo + per);
    for (int i = lo + t; i < hi; i += 256) {
        if (dst[i] == target) {
            int p = atomicAdd(&scnt, 1);
            if (p < CAP) g_edges[blockIdx.x * CAP + p] = i;
        }
    }
    __syncthreads();
    if (t == 0) g_cnt[blockIdx.x] = min(scnt, CAP);
}

// ---------------------------------------------------------------------------
// K3: one block, 1024 threads. Gather matched edges (parallel), sort (tiny),
// prefetch edge data (parallel), attention via warp-per-(edge,head), softmax,
// message sum, ReLU, FC with 4-way k-split.
__global__ void __launch_bounds__(1024, 1) compute_kernel(
    const float* __restrict__ x,
    const int*   __restrict__ src,
    const float* __restrict__ eattr,
    const float* __restrict__ Wl,  const float* __restrict__ bl,
    const float* __restrict__ Wr,  const float* __restrict__ br,
    const float* __restrict__ We,  const float* __restrict__ att,
    const float* __restrict__ bo,
    const float* __restrict__ Wfc, const float* __restrict__ bfc,
    float* __restrict__ out)
{
    __shared__ int   sCnts[G2];
    __shared__ int   sOff[G2];
    __shared__ int   sList[MAXED];
    __shared__ float sX0[MAXED], sX1[MAXED], sEa[MAXED];
    __shared__ float sXr[HC];
    __shared__ float sAlpha[MAXED * 2];
    __shared__ float sTe[HC];
    __shared__ float sP[1024];
    __shared__ int   sTot;

    const int t = threadIdx.x;

    // 1) gather per-block counts (one round trip)
    if (t < G2) sCnts[t] = g_cnt[t];
    __syncthreads();
    if (t == 0) {
        int tot = 0;
        for (int b = 0; b < G2; b++) { sOff[b] = tot; tot += sCnts[b]; }
        sTot = tot > MAXED ? MAXED : tot;
    }
    __syncthreads();
    const int cnt = sTot;

    // 2) copy matched edge ids (parallel over filter blocks)
    if (t < G2) {
        int o = sOff[t], c = sCnts[t];
        for (int i = 0; i < c; i++)
            if (o + i < MAXED) sList[o + i] = g_edges[t * CAP + i];
    }
    __syncthreads();

    // 3) sort ascending (bit-deterministic segment_sum order); cnt ~ 8
    if (t == 0) {
        for (int a = 1; a < cnt; a++) {
            int key = sList[a], b = a - 1;
            while (b >= 0 && sList[b] > key) { sList[b + 1] = sList[b]; b--; }
            sList[b + 1] = key;
        }
    }
    __syncthreads();

    // 4) prefetch edge data (2 dependent round trips, all in parallel)
    if (t < cnt) {
        const int eid = sList[t];
        const int s   = src[eid];
        sEa[t] = eattr[eid];
        sX0[t] = x[2 * s];
        sX1[t] = x[2 * s + 1];
    }
    // xr for target node (broadcast load of x[target])
    const int target = g_target;
    if (t < HC) {
        const float xt0 = x[2 * target], xt1 = x[2 * target + 1];
        sXr[t] = xt0 * Wr[t] + xt1 * Wr[HC + t] + br[t];
    }
    __syncthreads();

    // 5) attention logits: one warp per (edge, head); shuffle reduce
    {
        const int wid = t >> 5, lane = t & 31;
        for (int p = wid; p < 2 * cnt; p += 32) {
            const int e = p >> 1, h = p & 1;
            const float xs0 = sX0[e], xs1 = sX1[e], ea = sEa[e];
            float acc = 0.0f;
            #pragma unroll
            for (int i = 0; i < 4; i++) {
                const int c = h * 128 + lane + 32 * i;
                const float xl = xs0 * Wl[c] + xs1 * Wl[HC + c] + bl[c];
                float m = xl + sXr[c] + ea * We[c];
                float lv = m > 0.0f ? m : 0.2f * m;
                acc += lv * att[c];
            }
            #pragma unroll
            for (int st = 16; st > 0; st >>= 1)
                acc += __shfl_down_sync(0xFFFFFFFFu, acc, st);
            if (lane == 0) sAlpha[e * 2 + h] = acc;
        }
    }
    __syncthreads();

    // 6) per-head softmax over matched edges (reference quirks preserved)
    if (t < 2) {
        const int h = t;
        float amax = -INFINITY;
        for (int e = 0; e < cnt; e++) amax = fmaxf(amax, sAlpha[e * 2 + h]);
        if (!isfinite(amax)) amax = 0.0f;
        float den = 0.0f;
        for (int e = 0; e < cnt; e++) den += expf(sAlpha[e * 2 + h] - amax);
        const float inv = 1.0f / (den + 1e-16f);
        for (int e = 0; e < cnt; e++)
            sAlpha[e * 2 + h] = expf(sAlpha[e * 2 + h] - amax) * inv;
    }
    __syncthreads();

    // 7) weighted message sum, bias, ReLU (ascending edge order = ref order)
    if (t < HC) {
        const int j = t, h = j >> 7;
        const float Wl0 = Wl[j], Wl1 = Wl[HC + j], blj = bl[j];
        float acc = 0.0f;
        for (int e = 0; e < cnt; e++) {
            const float xl = sX0[e] * Wl0 + sX1[e] * Wl1 + blj;
            acc += xl * sAlpha[e * 2 + h];
        }
        sTe[j] = fmaxf(acc + bo[j], 0.0f);
    }
    __syncthreads();

    // 8) FC: out[j] = bfc[j] + sum_k te[k]*Wfc[k,j]; 4-way k-split for MLP
    {
        const int j = t & 255, g = t >> 8;
        const int k0 = g * 64;
        float acc = 0.0f;
        #pragma unroll 8
        for (int k = k0; k < k0 + 64; k++)
            acc += sTe[k] * Wfc[k * HID + j];
        sP[t] = acc;
    }
    __syncthreads();
    if (t < HID)
        out[t] = bfc[t] + ((sP[t] + sP[256 + t]) + (sP[512 + t] + sP[768 + t]));
}

// ---------------------------------------------------------------------------
extern "C" void kernel_launch(void* const* d_in, const int* in_sizes, int n_in,
                              void* d_out, int out_size)
{
    const float* x          = (const float*)d_in[0];
    const int*   edge_index = (const int*)  d_in[1];
    const float* edge_attr  = (const float*)d_in[2];
    const int*   labels     = (const int*)  d_in[3];
    // conv1 params d_in[4..10] are dead code (h1 overwritten in reference)
    const float* Wl2 = (const float*)d_in[11];
    const float* bl2 = (const float*)d_in[12];
    const float* Wr2 = (const float*)d_in[13];
    const float* br2 = (const float*)d_in[14];
    const float* We2 = (const float*)d_in[15];
    const float* att2= (const float*)d_in[16];
    const float* bo2 = (const float*)d_in[17];
    const float* Wfc = (const float*)d_in[18];
    const float* bfc = (const float*)d_in[19];
    float* out = (float*)d_out;

    const int N = in_sizes[0] / 2;
    const int E = in_sizes[1] / 2;
    const int* src = edge_index;
    const int* dst = edge_index + E;

    int nb1 = (N + 2047) / 2048;
    if (nb1 > MAXB1) nb1 = MAXB1;   // N=50K -> 25 blocks

    argmax_part_kernel<<<nb1, 256>>>(labels, N);
    filter_kernel<<<G2, 256>>>(dst, E, nb1);
    compute_kernel<<<1, 1024>>>(x, src, edge_attr,
                                Wl2, bl2, Wr2, br2, We2, att2, bo2,
                                Wfc, bfc, out);
}